// round 1
// baseline (speedup 1.0000x reference)
#include <cuda_runtime.h>
#include <math.h>

#define NTOK 4096
#define DIM  1024
#define HID  4096
#define NEXP 8
#define MAXA (NTOK * 2)

// -------- device scratch (static, allocation-free) --------
__device__ int   g_cnt[NEXP];
__device__ int   g_list[NEXP][MAXA];     // assignment ids (2*token+slot)
__device__ float g_wgt[MAXA];            // gate weight per assignment
__device__ float g_h[(size_t)MAXA * HID];  // 128 MB intermediate activations

// -------- phase 0: zero output + counters --------
__global__ void zero_kernel(float* __restrict__ out) {
    size_t i = ((size_t)blockIdx.x * blockDim.x + threadIdx.x) * 4;
    if (i < (size_t)NTOK * DIM)
        *reinterpret_cast<float4*>(out + i) = make_float4(0.f, 0.f, 0.f, 0.f);
    if (blockIdx.x == 0 && threadIdx.x < NEXP) g_cnt[threadIdx.x] = 0;
}

// -------- phase 1: gating (1 warp per token) --------
__global__ void gating_kernel(const float* __restrict__ x,
                              const float* __restrict__ Wg,
                              const float* __restrict__ bg) {
    int tok  = (blockIdx.x * blockDim.x + threadIdx.x) >> 5;
    int lane = threadIdx.x & 31;
    if (tok >= NTOK) return;
    const float* xr = x + (size_t)tok * DIM;

    float acc[NEXP];
#pragma unroll
    for (int e = 0; e < NEXP; e++) acc[e] = 0.f;

    for (int d = lane; d < DIM; d += 32) {
        float xv = xr[d];
        const float* wr = Wg + d * NEXP;
#pragma unroll
        for (int e = 0; e < NEXP; e++) acc[e] += xv * wr[e];
    }
#pragma unroll
    for (int off = 16; off; off >>= 1) {
#pragma unroll
        for (int e = 0; e < NEXP; e++)
            acc[e] += __shfl_xor_sync(0xffffffffu, acc[e], off);
    }

    if (lane == 0) {
        float logit[NEXP], m = -1e30f;
#pragma unroll
        for (int e = 0; e < NEXP; e++) {
            logit[e] = acc[e] + bg[e];
            m = fmaxf(m, logit[e]);
        }
        float p[NEXP], s = 0.f;
#pragma unroll
        for (int e = 0; e < NEXP; e++) { p[e] = expf(logit[e] - m); s += p[e]; }
        float inv = 1.f / s;
#pragma unroll
        for (int e = 0; e < NEXP; e++) p[e] *= inv;

        // top-2 (lower index wins ties, matching lax.top_k)
        int e0 = 0;
#pragma unroll
        for (int e = 1; e < NEXP; e++) if (p[e] > p[e0]) e0 = e;
        int e1 = (e0 == 0) ? 1 : 0;
#pragma unroll
        for (int e = 0; e < NEXP; e++)
            if (e != e0 && p[e] > p[e1]) e1 = e;

        g_wgt[2 * tok + 0] = p[e0];
        g_wgt[2 * tok + 1] = p[e1];
        int p0 = atomicAdd(&g_cnt[e0], 1);
        g_list[e0][p0] = 2 * tok + 0;
        int p1 = atomicAdd(&g_cnt[e1], 1);
        g_list[e1][p1] = 2 * tok + 1;
    }
}

// -------- phases 2/3: gathered per-expert GEMM --------
// PHASE1: h[a] = relu(x[tok(a)] @ W1[e] + b1[e])  (K=DIM,  N=HID)
// PHASE2: out[tok(a)] += w_a * (h[a] @ W2[e] + b2[e])  (K=HID, N=DIM)
template <bool PHASE1>
__global__ void __launch_bounds__(256)
expert_gemm(const float* __restrict__ x,
            const float* __restrict__ W,
            const float* __restrict__ bias,
            float* __restrict__ out) {
    constexpr int K  = PHASE1 ? DIM : HID;
    constexpr int NT = PHASE1 ? HID : DIM;
    constexpr int BM = 128, BN = 64, BK = 16;

    const int e   = blockIdx.z;
    const int cnt = g_cnt[e];
    const int m0  = blockIdx.y * BM;
    if (m0 >= cnt) return;
    const int n0 = blockIdx.x * BN;

    __shared__ float As[BK][BM + 4];   // A stored transposed, padded
    __shared__ float Bs[BK][BN];

    const int tid = threadIdx.x;
    const int tr  = (tid >> 4) * 8;    // 16 row groups of 8
    const int tc  = (tid & 15) * 4;    // 16 col groups of 4

    // --- A load slots: 2 float4s per thread (128 rows x 4 quads) ---
    const float* aptr[2];
    int akc[2], arw[2];
#pragma unroll
    for (int j = 0; j < 2; j++) {
        int s  = tid + j * 256;
        int r  = s >> 2;
        int kc = (s & 3) * 4;
        arw[j] = r;
        akc[j] = kc;
        int idx = m0 + r;
        if (idx < cnt) {
            int a = g_list[e][idx];
            aptr[j] = PHASE1 ? (x + (size_t)(a >> 1) * DIM + kc)
                             : (g_h + (size_t)a * HID + kc);
        } else {
            aptr[j] = nullptr;
        }
    }
    // --- B load slot: 1 float4 per thread (16 x 64) ---
    const int bk = tid >> 4;
    const int bn = (tid & 15) * 4;
    const float* bptr = W + ((size_t)e * K + bk) * NT + n0 + bn;

    float acc[8][4];
#pragma unroll
    for (int i = 0; i < 8; i++)
#pragma unroll
        for (int j = 0; j < 4; j++) acc[i][j] = 0.f;

    for (int k0 = 0; k0 < K; k0 += BK) {
#pragma unroll
        for (int j = 0; j < 2; j++) {
            float4 v = make_float4(0.f, 0.f, 0.f, 0.f);
            if (aptr[j]) v = *reinterpret_cast<const float4*>(aptr[j] + k0);
            As[akc[j] + 0][arw[j]] = v.x;
            As[akc[j] + 1][arw[j]] = v.y;
            As[akc[j] + 2][arw[j]] = v.z;
            As[akc[j] + 3][arw[j]] = v.w;
        }
        *reinterpret_cast<float4*>(&Bs[bk][bn]) =
            *reinterpret_cast<const float4*>(bptr + (size_t)k0 * NT);
        __syncthreads();

#pragma unroll
        for (int k = 0; k < BK; k++) {
            float4 a0 = *reinterpret_cast<const float4*>(&As[k][tr]);
            float4 a1 = *reinterpret_cast<const float4*>(&As[k][tr + 4]);
            float4 b  = *reinterpret_cast<const float4*>(&Bs[k][tc]);
            float av[8] = {a0.x, a0.y, a0.z, a0.w, a1.x, a1.y, a1.z, a1.w};
            float bv[4] = {b.x, b.y, b.z, b.w};
#pragma unroll
            for (int i = 0; i < 8; i++)
#pragma unroll
                for (int j = 0; j < 4; j++)
                    acc[i][j] = fmaf(av[i], bv[j], acc[i][j]);
        }
        __syncthreads();
    }

    const float* bp = bias + (size_t)e * NT + n0 + tc;
    if (PHASE1) {
#pragma unroll
        for (int i = 0; i < 8; i++) {
            int idx = m0 + tr + i;
            if (idx < cnt) {
                int a = g_list[e][idx];
                float* hp = g_h + (size_t)a * HID + n0 + tc;
                float4 v;
                v.x = fmaxf(acc[i][0] + bp[0], 0.f);
                v.y = fmaxf(acc[i][1] + bp[1], 0.f);
                v.z = fmaxf(acc[i][2] + bp[2], 0.f);
                v.w = fmaxf(acc[i][3] + bp[3], 0.f);
                *reinterpret_cast<float4*>(hp) = v;
            }
        }
    } else {
#pragma unroll
        for (int i = 0; i < 8; i++) {
            int idx = m0 + tr + i;
            if (idx < cnt) {
                int a = g_list[e][idx];
                float w = g_wgt[a];
                int t = a >> 1;
                float* op = out + (size_t)t * DIM + n0 + tc;
                atomicAdd(&op[0], (acc[i][0] + bp[0]) * w);
                atomicAdd(&op[1], (acc[i][1] + bp[1]) * w);
                atomicAdd(&op[2], (acc[i][2] + bp[2]) * w);
                atomicAdd(&op[3], (acc[i][3] + bp[3]) * w);
            }
        }
    }
}

extern "C" void kernel_launch(void* const* d_in, const int* in_sizes, int n_in,
                              void* d_out, int out_size) {
    const float* x  = (const float*)d_in[0];
    const float* Wg = (const float*)d_in[1];
    const float* bg = (const float*)d_in[2];
    const float* W1 = (const float*)d_in[3];
    const float* b1 = (const float*)d_in[4];
    const float* W2 = (const float*)d_in[5];
    const float* b2 = (const float*)d_in[6];
    float* out = (float*)d_out;

    // phase 0: zero output + expert counters
    zero_kernel<<<(NTOK * DIM) / (256 * 4), 256>>>(out);
    // phase 1: gating (1 warp / token)
    gating_kernel<<<(NTOK * 32) / 256, 256>>>(x, Wg, bg);
    // phase 2: h = relu(gather(x) @ W1 + b1)
    expert_gemm<true><<<dim3(HID / 64, MAXA / 128, NEXP), 256>>>(x, W1, b1, nullptr);
    // phase 3: out += w * (h @ W2 + b2)
    expert_gemm<false><<<dim3(DIM / 64, MAXA / 128, NEXP), 256>>>(x, W2, b2, out);
}

// round 3
// speedup vs baseline: 2.1900x; 2.1900x over previous
#include <cuda_runtime.h>
#include <cuda_bf16.h>
#include <cstdint>
#include <math.h>

#define NTOK 4096
#define DIM  1024
#define HID  4096
#define NEXP 8
#define MAXA (NTOK * 2)

// ---------------- device scratch (static, allocation-free) ----------------
__device__ int   g_cnt[NEXP];
__device__ int   g_list[NEXP][MAXA];
__device__ float g_wgt[MAXA];
__device__ __nv_bfloat16 g_x_hi[(size_t)NTOK * DIM];
__device__ __nv_bfloat16 g_x_lo[(size_t)NTOK * DIM];
__device__ __nv_bfloat16 g_w1_hi[(size_t)NEXP * HID * DIM];   // [e][h][d] (n-major rows of k)
__device__ __nv_bfloat16 g_w1_lo[(size_t)NEXP * HID * DIM];
__device__ __nv_bfloat16 g_w2_hi[(size_t)NEXP * DIM * HID];   // [e][d][h]
__device__ __nv_bfloat16 g_w2_lo[(size_t)NEXP * DIM * HID];
__device__ __nv_bfloat16 g_h_hi[(size_t)MAXA * HID];
__device__ __nv_bfloat16 g_h_lo[(size_t)MAXA * HID];

// ---------------- helpers ----------------
__device__ __forceinline__ uint32_t smem_u32(const void* p) {
    uint32_t a;
    asm("{ .reg .u64 t; cvta.to.shared.u64 t, %1; cvt.u32.u64 %0, t; }" : "=r"(a) : "l"(p));
    return a;
}
__device__ __forceinline__ void cp16(uint32_t dst, const void* src, uint32_t srcsz) {
    asm volatile("cp.async.cg.shared.global [%0], [%1], 16, %2;"
                 :: "r"(dst), "l"(src), "r"(srcsz) : "memory");
}
#define CP_COMMIT() asm volatile("cp.async.commit_group;" ::: "memory")
#define CP_WAIT(n)  asm volatile("cp.async.wait_group %0;" :: "n"(n) : "memory")

__device__ __forceinline__ void ldsm4(uint32_t* r, uint32_t addr) {
    asm volatile("ldmatrix.sync.aligned.m8n8.x4.shared.b16 {%0,%1,%2,%3}, [%4];"
                 : "=r"(r[0]), "=r"(r[1]), "=r"(r[2]), "=r"(r[3]) : "r"(addr));
}
__device__ __forceinline__ void mma16816(float* c, const uint32_t* a, uint32_t b0, uint32_t b1) {
    asm volatile(
        "mma.sync.aligned.m16n8k16.row.col.f32.bf16.bf16.f32 "
        "{%0,%1,%2,%3}, {%4,%5,%6,%7}, {%8,%9}, {%0,%1,%2,%3};"
        : "+f"(c[0]), "+f"(c[1]), "+f"(c[2]), "+f"(c[3])
        : "r"(a[0]), "r"(a[1]), "r"(a[2]), "r"(a[3]), "r"(b0), "r"(b1));
}
__device__ __forceinline__ uint32_t pack_bf2(float a, float b) {
    __nv_bfloat162 t = __floats2bfloat162_rn(a, b);
    return *reinterpret_cast<uint32_t*>(&t);
}
#define SWZ(o) ((o) ^ (((o) >> 3) & 0x70))

// ---------------- phase 0: zero out + counters ----------------
__global__ void zero_kernel(float* __restrict__ out) {
    size_t i = ((size_t)blockIdx.x * blockDim.x + threadIdx.x) * 4;
    if (i < (size_t)NTOK * DIM)
        *reinterpret_cast<float4*>(out + i) = make_float4(0.f, 0.f, 0.f, 0.f);
    if (blockIdx.x == 0 && threadIdx.x < NEXP) g_cnt[threadIdx.x] = 0;
}

// ---------------- split-convert x -> bf16 hi/lo ----------------
__global__ void conv_x(const float* __restrict__ x) {
    size_t i = ((size_t)blockIdx.x * blockDim.x + threadIdx.x) * 8;
    float v[8];
    *reinterpret_cast<float4*>(v)     = *reinterpret_cast<const float4*>(x + i);
    *reinterpret_cast<float4*>(v + 4) = *reinterpret_cast<const float4*>(x + i + 4);
    uint32_t ph[4], pl[4];
#pragma unroll
    for (int j = 0; j < 4; j++) {
        float a = v[2 * j], b = v[2 * j + 1];
        __nv_bfloat16 ha = __float2bfloat16(a), hb = __float2bfloat16(b);
        ph[j] = pack_bf2(a, b);
        pl[j] = pack_bf2(a - __bfloat162float(ha), b - __bfloat162float(hb));
    }
    *reinterpret_cast<uint4*>(g_x_hi + i) = make_uint4(ph[0], ph[1], ph[2], ph[3]);
    *reinterpret_cast<uint4*>(g_x_lo + i) = make_uint4(pl[0], pl[1], pl[2], pl[3]);
}

// ---------------- transpose-convert W [e][R][C] -> [e][C][R] bf16 hi/lo ----------------
__global__ void conv_w(const float* __restrict__ src, __nv_bfloat16* __restrict__ dh,
                       __nv_bfloat16* __restrict__ dl, int R, int C) {
    __shared__ float t[32][33];
    int e  = blockIdx.z;
    int r0 = blockIdx.y * 32, c0 = blockIdx.x * 32;
    int tx = threadIdx.x, ty = threadIdx.y;
    const float* sp = src + (size_t)e * R * C;
#pragma unroll
    for (int j = 0; j < 4; j++)
        t[ty + 8 * j][tx] = sp[(size_t)(r0 + ty + 8 * j) * C + c0 + tx];
    __syncthreads();
#pragma unroll
    for (int j = 0; j < 4; j++) {
        float v = t[tx][ty + 8 * j];
        __nv_bfloat16 hi = __float2bfloat16(v);
        float lo = v - __bfloat162float(hi);
        size_t o = ((size_t)e * C + c0 + ty + 8 * j) * R + r0 + tx;
        dh[o] = hi;
        dl[o] = __float2bfloat16(lo);
    }
}

// ---------------- gating (1 warp / token) ----------------
__global__ void gating_kernel(const float* __restrict__ x,
                              const float* __restrict__ Wg,
                              const float* __restrict__ bg) {
    int tok  = (blockIdx.x * blockDim.x + threadIdx.x) >> 5;
    int lane = threadIdx.x & 31;
    if (tok >= NTOK) return;
    const float* xr = x + (size_t)tok * DIM;
    float acc[NEXP];
#pragma unroll
    for (int e = 0; e < NEXP; e++) acc[e] = 0.f;
    for (int d = lane; d < DIM; d += 32) {
        float xv = xr[d];
        const float* wr = Wg + d * NEXP;
#pragma unroll
        for (int e = 0; e < NEXP; e++) acc[e] += xv * wr[e];
    }
#pragma unroll
    for (int off = 16; off; off >>= 1)
#pragma unroll
        for (int e = 0; e < NEXP; e++)
            acc[e] += __shfl_xor_sync(0xffffffffu, acc[e], off);
    if (lane == 0) {
        float logit[NEXP], m = -1e30f;
#pragma unroll
        for (int e = 0; e < NEXP; e++) { logit[e] = acc[e] + bg[e]; m = fmaxf(m, logit[e]); }
        float p[NEXP], s = 0.f;
#pragma unroll
        for (int e = 0; e < NEXP; e++) { p[e] = expf(logit[e] - m); s += p[e]; }
        float inv = 1.f / s;
#pragma unroll
        for (int e = 0; e < NEXP; e++) p[e] *= inv;
        int e0 = 0;
#pragma unroll
        for (int e = 1; e < NEXP; e++) if (p[e] > p[e0]) e0 = e;
        int e1 = (e0 == 0) ? 1 : 0;
#pragma unroll
        for (int e = 0; e < NEXP; e++) if (e != e0 && p[e] > p[e1]) e1 = e;
        g_wgt[2 * tok + 0] = p[e0];
        g_wgt[2 * tok + 1] = p[e1];
        int p0 = atomicAdd(&g_cnt[e0], 1); g_list[e0][p0] = 2 * tok + 0;
        int p1 = atomicAdd(&g_cnt[e1], 1); g_list[e1][p1] = 2 * tok + 1;
    }
}

// ---------------- HMMA split-bf16 gathered GEMM ----------------
// PHASE1: h = relu(x @ W1t^T + b1)    (K=DIM,  N=HID)
// PHASE2: out += w * (h @ W2t^T + b2) (K=HID,  N=DIM)
// CTA 128x128, 256 thr, warps 4(m) x 2(n), warp tile 32x64, K-chunk 64,
// 2-stage cp.async double buffer, SW128 xor swizzle, ldmatrix + mma.sync bf16.
template <bool PHASE1>
__global__ void __launch_bounds__(256, 1)
moe_gemm(const float* __restrict__ bias, float* __restrict__ out) {
    constexpr int KD  = PHASE1 ? DIM : HID;
    constexpr int ND  = PHASE1 ? HID : DIM;
    constexpr int NCH = KD / 64;
    constexpr int STG = 64 * 1024;   // bytes per stage: Ah|Al|Bh|Bl of 16KB each

    const __nv_bfloat16* Ah = PHASE1 ? g_x_hi : g_h_hi;
    const __nv_bfloat16* Al = PHASE1 ? g_x_lo : g_h_lo;
    const __nv_bfloat16* Bh = PHASE1 ? g_w1_hi : g_w2_hi;
    const __nv_bfloat16* Bl = PHASE1 ? g_w1_lo : g_w2_lo;

    const int e   = blockIdx.z;
    const int cnt = g_cnt[e];
    const int m0  = blockIdx.y * 128;
    if (m0 >= cnt) return;
    const int n0  = blockIdx.x * 128;
    const int tid = threadIdx.x;

    extern __shared__ char smraw[];
    char* tilep = (char*)(((uintptr_t)smraw + 1023) & ~(uintptr_t)1023);
    const uint32_t sbase = smem_u32(tilep);
    __shared__ float s_bias[128];
    if (tid < 128) s_bias[tid] = bias[(size_t)e * ND + n0 + tid];

    // ---- load mapping: thread covers 16B seg (t&7) of rows (t>>3)+32p ----
    const int seg = tid & 7;
    const int rg  = tid >> 3;
    size_t   aoff[4], boff[4];
    uint32_t avalid[4], swzo[4];
#pragma unroll
    for (int p = 0; p < 4; p++) {
        int r   = rg + 32 * p;
        int idx = m0 + r;
        int a   = (idx < cnt) ? g_list[e][idx] : 0;
        int ra  = PHASE1 ? (a >> 1) : a;
        avalid[p] = (idx < cnt) ? 16u : 0u;
        aoff[p]   = (size_t)ra * KD + seg * 8;
        boff[p]   = ((size_t)e * ND + n0 + r) * KD + seg * 8;
        int o     = r * 128 + seg * 16;
        swzo[p]   = SWZ(o);
    }

    // ---- fragment addressing ----
    const int lane = tid & 31;
    const int wid  = tid >> 5;
    const int wm   = wid >> 1;       // 0..3  (m offset wm*32)
    const int wn   = wid & 1;        // 0..1  (n offset wn*64)
    uint32_t abase[2], axor[2], bbase[4], bxor[4];
#pragma unroll
    for (int mf = 0; mf < 2; mf++) {
        int row   = wm * 32 + mf * 16 + (lane & 15);
        abase[mf] = row * 128 + (lane >> 4) * 16;
        axor[mf]  = (row & 7) << 4;
    }
#pragma unroll
    for (int p = 0; p < 4; p++) {
        int row  = wn * 64 + p * 16 + (lane & 15);
        bbase[p] = row * 128 + (lane >> 4) * 16;
        bxor[p]  = (row & 7) << 4;
    }

    float acc[2][8][4];
#pragma unroll
    for (int i = 0; i < 2; i++)
#pragma unroll
        for (int j = 0; j < 8; j++)
#pragma unroll
            for (int q = 0; q < 4; q++) acc[i][j][q] = 0.f;

    // ---- prologue: load chunk 0 ----
    {
        const size_t koff = 0;
        uint32_t sb = sbase;
#pragma unroll
        for (int p = 0; p < 4; p++) {
            cp16(sb + swzo[p],          Ah + aoff[p] + koff, avalid[p]);
            cp16(sb + 16384 + swzo[p],  Al + aoff[p] + koff, avalid[p]);
            cp16(sb + 32768 + swzo[p],  Bh + boff[p] + koff, 16u);
            cp16(sb + 49152 + swzo[p],  Bl + boff[p] + koff, 16u);
        }
        CP_COMMIT();
    }

    for (int c = 0; c < NCH; ++c) {
        if (c + 1 < NCH) {
            const size_t koff = (size_t)(c + 1) * 64;
            uint32_t sb = sbase + ((c + 1) & 1) * STG;
#pragma unroll
            for (int p = 0; p < 4; p++) {
                cp16(sb + swzo[p],          Ah + aoff[p] + koff, avalid[p]);
                cp16(sb + 16384 + swzo[p],  Al + aoff[p] + koff, avalid[p]);
                cp16(sb + 32768 + swzo[p],  Bh + boff[p] + koff, 16u);
                cp16(sb + 49152 + swzo[p],  Bl + boff[p] + koff, 16u);
            }
            CP_COMMIT();
            CP_WAIT(1);
        } else {
            CP_WAIT(0);
        }
        __syncthreads();

        const uint32_t sb = sbase + (c & 1) * STG;
#pragma unroll
        for (int kk = 0; kk < 4; kk++) {
            uint32_t ah[2][4], al[2][4], bh[4][4], bl[4][4];
#pragma unroll
            for (int mf = 0; mf < 2; mf++) {
                uint32_t o = (abase[mf] + kk * 32) ^ axor[mf];
                ldsm4(ah[mf], sb + o);
                ldsm4(al[mf], sb + 16384 + o);
            }
#pragma unroll
            for (int p = 0; p < 4; p++) {
                uint32_t o = (bbase[p] + kk * 32) ^ bxor[p];
                ldsm4(bh[p], sb + 32768 + o);
                ldsm4(bl[p], sb + 49152 + o);
            }
#pragma unroll
            for (int mf = 0; mf < 2; mf++)
#pragma unroll
                for (int p = 0; p < 4; p++) {
                    mma16816(acc[mf][2 * p],     ah[mf], bh[p][0], bh[p][2]);
                    mma16816(acc[mf][2 * p + 1], ah[mf], bh[p][1], bh[p][3]);
                    mma16816(acc[mf][2 * p],     ah[mf], bl[p][0], bl[p][2]);
                    mma16816(acc[mf][2 * p + 1], ah[mf], bl[p][1], bl[p][3]);
                    mma16816(acc[mf][2 * p],     al[mf], bh[p][0], bh[p][2]);
                    mma16816(acc[mf][2 * p + 1], al[mf], bh[p][1], bh[p][3]);
                }
        }
        __syncthreads();
    }

    // ---- epilogue ----
    const int quad = lane >> 2;
    const int qid  = lane & 3;
    const int ncol0 = wn * 64;     // CTA-local n base for this warp

#pragma unroll
    for (int mf = 0; mf < 2; mf++) {
#pragma unroll
        for (int rv = 0; rv < 2; rv++) {           // +0 / +8 rows
            int midx = m0 + wm * 32 + mf * 16 + rv * 8 + quad;
            if (midx >= cnt) continue;
            int a = g_list[e][midx];
            if (PHASE1) {
                __nv_bfloat16* dh = g_h_hi + (size_t)a * HID + n0;
                __nv_bfloat16* dl = g_h_lo + (size_t)a * HID + n0;
#pragma unroll
                for (int nf = 0; nf < 8; nf++) {
                    int nloc = ncol0 + nf * 8 + 2 * qid;
                    float v0 = fmaxf(acc[mf][nf][2 * rv]     + s_bias[nloc],     0.f);
                    float v1 = fmaxf(acc[mf][nf][2 * rv + 1] + s_bias[nloc + 1], 0.f);
                    __nv_bfloat16 h0 = __float2bfloat16(v0), h1 = __float2bfloat16(v1);
                    *reinterpret_cast<uint32_t*>(dh + nloc) = pack_bf2(v0, v1);
                    *reinterpret_cast<uint32_t*>(dl + nloc) =
                        pack_bf2(v0 - __bfloat162float(h0), v1 - __bfloat162float(h1));
                }
            } else {
                float w = g_wgt[a];
                float* op = out + (size_t)(a >> 1) * DIM + n0;
#pragma unroll
                for (int nf = 0; nf < 8; nf++) {
                    int nloc = ncol0 + nf * 8 + 2 * qid;
                    atomicAdd(op + nloc,     (acc[mf][nf][2 * rv]     + s_bias[nloc])     * w);
                    atomicAdd(op + nloc + 1, (acc[mf][nf][2 * rv + 1] + s_bias[nloc + 1]) * w);
                }
            }
        }
    }
}

// ---------------- launch ----------------
extern "C" void kernel_launch(void* const* d_in, const int* in_sizes, int n_in,
                              void* d_out, int out_size) {
    const float* x  = (const float*)d_in[0];
    const float* Wg = (const float*)d_in[1];
    const float* bg = (const float*)d_in[2];
    const float* W1 = (const float*)d_in[3];
    const float* b1 = (const float*)d_in[4];
    const float* W2 = (const float*)d_in[5];
    const float* b2 = (const float*)d_in[6];
    float* out = (float*)d_out;

    const int SMEM_BYTES = 2 * 64 * 1024 + 1024;
    cudaFuncSetAttribute((const void*)moe_gemm<true>,
                         cudaFuncAttributeMaxDynamicSharedMemorySize, SMEM_BYTES);
    cudaFuncSetAttribute((const void*)moe_gemm<false>,
                         cudaFuncAttributeMaxDynamicSharedMemorySize, SMEM_BYTES);

    __nv_bfloat16 *w1h, *w1l, *w2h, *w2l;
    cudaGetSymbolAddress((void**)&w1h, g_w1_hi);
    cudaGetSymbolAddress((void**)&w1l, g_w1_lo);
    cudaGetSymbolAddress((void**)&w2h, g_w2_hi);
    cudaGetSymbolAddress((void**)&w2l, g_w2_lo);

    zero_kernel<<<(NTOK * DIM) / (256 * 4), 256>>>(out);
    conv_x<<<(NTOK * DIM) / (256 * 8), 256>>>(x);
    // W1 [e][D][H] -> [e][H][D];  W2 [e][H][D] -> [e][D][H]
    conv_w<<<dim3(HID / 32, DIM / 32, NEXP), dim3(32, 8)>>>(W1, w1h, w1l, DIM, HID);
    conv_w<<<dim3(DIM / 32, HID / 32, NEXP), dim3(32, 8)>>>(W2, w2h, w2l, HID, DIM);
    gating_kernel<<<(NTOK * 32) / 256, 256>>>(x, Wg, bg);

    moe_gemm<true><<<dim3(HID / 128, MAXA / 128, NEXP), 256, SMEM_BYTES>>>(b1, nullptr);
    moe_gemm<false><<<dim3(DIM / 128, MAXA / 128, NEXP), 256, SMEM_BYTES>>>(b2, out);
}

// round 4
// speedup vs baseline: 2.2400x; 1.0228x over previous
#include <cuda_runtime.h>
#include <cuda_bf16.h>
#include <cstdint>
#include <math.h>

#define NTOK 4096
#define DIM  1024
#define HID  4096
#define NEXP 8
#define MAXA (NTOK * 2)

// ---------------- device scratch (static, allocation-free) ----------------
__device__ int   g_cnt[NEXP];
__device__ int   g_list[NEXP][MAXA];
__device__ float g_wgt[MAXA];
__device__ __nv_bfloat16 g_x_hi[(size_t)NTOK * DIM];
__device__ __nv_bfloat16 g_x_lo[(size_t)NTOK * DIM];
__device__ __nv_bfloat16 g_w1_hi[(size_t)NEXP * HID * DIM];   // [e][h][d] (n-major rows of k)
__device__ __nv_bfloat16 g_w1_lo[(size_t)NEXP * HID * DIM];
__device__ __nv_bfloat16 g_w2_hi[(size_t)NEXP * DIM * HID];   // [e][d][h]
__device__ __nv_bfloat16 g_w2_lo[(size_t)NEXP * DIM * HID];
__device__ __nv_bfloat16 g_h_hi[(size_t)MAXA * HID];
__device__ __nv_bfloat16 g_h_lo[(size_t)MAXA * HID];

// ---------------- helpers ----------------
__device__ __forceinline__ uint32_t smem_u32(const void* p) {
    uint32_t a;
    asm("{ .reg .u64 t; cvta.to.shared.u64 t, %1; cvt.u32.u64 %0, t; }" : "=r"(a) : "l"(p));
    return a;
}
__device__ __forceinline__ void cp16(uint32_t dst, const void* src, uint32_t srcsz) {
    asm volatile("cp.async.cg.shared.global [%0], [%1], 16, %2;"
                 :: "r"(dst), "l"(src), "r"(srcsz) : "memory");
}
#define CP_COMMIT() asm volatile("cp.async.commit_group;" ::: "memory")
#define CP_WAIT(n)  asm volatile("cp.async.wait_group %0;" :: "n"(n) : "memory")

__device__ __forceinline__ void ldsm4(uint32_t* r, uint32_t addr) {
    asm volatile("ldmatrix.sync.aligned.m8n8.x4.shared.b16 {%0,%1,%2,%3}, [%4];"
                 : "=r"(r[0]), "=r"(r[1]), "=r"(r[2]), "=r"(r[3]) : "r"(addr));
}
__device__ __forceinline__ void mma16816(float* c, const uint32_t* a, uint32_t b0, uint32_t b1) {
    asm volatile(
        "mma.sync.aligned.m16n8k16.row.col.f32.bf16.bf16.f32 "
        "{%0,%1,%2,%3}, {%4,%5,%6,%7}, {%8,%9}, {%0,%1,%2,%3};"
        : "+f"(c[0]), "+f"(c[1]), "+f"(c[2]), "+f"(c[3])
        : "r"(a[0]), "r"(a[1]), "r"(a[2]), "r"(a[3]), "r"(b0), "r"(b1));
}
__device__ __forceinline__ uint32_t pack_bf2(float a, float b) {
    __nv_bfloat162 t = __floats2bfloat162_rn(a, b);
    return *reinterpret_cast<uint32_t*>(&t);
}
#define SWZ(o) ((o) ^ (((o) >> 3) & 0x70))

// ---------------- phase 0: zero out + counters ----------------
__global__ void zero_kernel(float* __restrict__ out) {
    size_t i = ((size_t)blockIdx.x * blockDim.x + threadIdx.x) * 4;
    if (i < (size_t)NTOK * DIM)
        *reinterpret_cast<float4*>(out + i) = make_float4(0.f, 0.f, 0.f, 0.f);
    if (blockIdx.x == 0 && threadIdx.x < NEXP) g_cnt[threadIdx.x] = 0;
}

// ---------------- split-convert x -> bf16 hi/lo ----------------
__global__ void conv_x(const float* __restrict__ x) {
    size_t i = ((size_t)blockIdx.x * blockDim.x + threadIdx.x) * 8;
    float v[8];
    *reinterpret_cast<float4*>(v)     = *reinterpret_cast<const float4*>(x + i);
    *reinterpret_cast<float4*>(v + 4) = *reinterpret_cast<const float4*>(x + i + 4);
    uint32_t ph[4], pl[4];
#pragma unroll
    for (int j = 0; j < 4; j++) {
        float a = v[2 * j], b = v[2 * j + 1];
        __nv_bfloat16 ha = __float2bfloat16(a), hb = __float2bfloat16(b);
        ph[j] = pack_bf2(a, b);
        pl[j] = pack_bf2(a - __bfloat162float(ha), b - __bfloat162float(hb));
    }
    *reinterpret_cast<uint4*>(g_x_hi + i) = make_uint4(ph[0], ph[1], ph[2], ph[3]);
    *reinterpret_cast<uint4*>(g_x_lo + i) = make_uint4(pl[0], pl[1], pl[2], pl[3]);
}

// ------- transpose-convert W [e][R][C] -> [e][C][R] bf16 hi/lo (packed stores) -------
__global__ void conv_w(const float* __restrict__ src, __nv_bfloat16* __restrict__ dh,
                       __nv_bfloat16* __restrict__ dl, int R, int C) {
    __shared__ float t[32][33];
    int e  = blockIdx.z;
    int r0 = blockIdx.y * 32, c0 = blockIdx.x * 32;
    int tx = threadIdx.x;   // 0..15
    int ty = threadIdx.y;   // 0..15
    const float* sp = src + (size_t)e * R * C;
#pragma unroll
    for (int j = 0; j < 2; j++) {
        int r = ty + 16 * j;
        float2 v = *reinterpret_cast<const float2*>(sp + (size_t)(r0 + r) * C + c0 + 2 * tx);
        t[r][2 * tx]     = v.x;
        t[r][2 * tx + 1] = v.y;
    }
    __syncthreads();
#pragma unroll
    for (int j = 0; j < 2; j++) {
        int cc = ty + 16 * j;
        float v0 = t[2 * tx][cc], v1 = t[2 * tx + 1][cc];
        __nv_bfloat16 h0 = __float2bfloat16(v0), h1 = __float2bfloat16(v1);
        size_t o = ((size_t)e * C + c0 + cc) * R + r0 + 2 * tx;
        *reinterpret_cast<uint32_t*>(dh + o) = pack_bf2(v0, v1);
        *reinterpret_cast<uint32_t*>(dl + o) =
            pack_bf2(v0 - __bfloat162float(h0), v1 - __bfloat162float(h1));
    }
}

// ---------------- gating (1 warp / token) ----------------
__global__ void gating_kernel(const float* __restrict__ x,
                              const float* __restrict__ Wg,
                              const float* __restrict__ bg) {
    int tok  = (blockIdx.x * blockDim.x + threadIdx.x) >> 5;
    int lane = threadIdx.x & 31;
    if (tok >= NTOK) return;
    const float* xr = x + (size_t)tok * DIM;
    float acc[NEXP];
#pragma unroll
    for (int e = 0; e < NEXP; e++) acc[e] = 0.f;
    for (int d = lane; d < DIM; d += 32) {
        float xv = xr[d];
        const float* wr = Wg + d * NEXP;
#pragma unroll
        for (int e = 0; e < NEXP; e++) acc[e] += xv * wr[e];
    }
#pragma unroll
    for (int off = 16; off; off >>= 1)
#pragma unroll
        for (int e = 0; e < NEXP; e++)
            acc[e] += __shfl_xor_sync(0xffffffffu, acc[e], off);
    if (lane == 0) {
        float logit[NEXP], m = -1e30f;
#pragma unroll
        for (int e = 0; e < NEXP; e++) { logit[e] = acc[e] + bg[e]; m = fmaxf(m, logit[e]); }
        float p[NEXP], s = 0.f;
#pragma unroll
        for (int e = 0; e < NEXP; e++) { p[e] = expf(logit[e] - m); s += p[e]; }
        float inv = 1.f / s;
#pragma unroll
        for (int e = 0; e < NEXP; e++) p[e] *= inv;
        int e0 = 0;
#pragma unroll
        for (int e = 1; e < NEXP; e++) if (p[e] > p[e0]) e0 = e;
        int e1 = (e0 == 0) ? 1 : 0;
#pragma unroll
        for (int e = 0; e < NEXP; e++) if (e != e0 && p[e] > p[e1]) e1 = e;
        g_wgt[2 * tok + 0] = p[e0];
        g_wgt[2 * tok + 1] = p[e1];
        int p0 = atomicAdd(&g_cnt[e0], 1); g_list[e0][p0] = 2 * tok + 0;
        int p1 = atomicAdd(&g_cnt[e1], 1); g_list[e1][p1] = 2 * tok + 1;
    }
}

// ---------------- HMMA split-bf16 gathered GEMM ----------------
// PHASE1: h = relu(x @ W1t^T + b1)    (K=DIM,  N=HID)
// PHASE2: out += w * (h @ W2t^T + b2) (K=HID,  N=DIM)
// CTA 128x128, 256 thr, warps 4(m) x 2(n), warp tile 32x64, K-chunk 64,
// 2-stage cp.async double buffer, SW128 xor swizzle, ldmatrix + mma.sync bf16.
// MMA issue order is TERM-OUTERMOST so same-accumulator reuse distance is 16
// instructions (covers HMMA acc RAW latency).
template <bool PHASE1>
__global__ void __launch_bounds__(256, 1)
moe_gemm(const float* __restrict__ bias, float* __restrict__ out) {
    constexpr int KD  = PHASE1 ? DIM : HID;
    constexpr int ND  = PHASE1 ? HID : DIM;
    constexpr int NCH = KD / 64;
    constexpr int STG = 64 * 1024;   // bytes per stage: Ah|Al|Bh|Bl of 16KB each

    const __nv_bfloat16* Ah = PHASE1 ? g_x_hi : g_h_hi;
    const __nv_bfloat16* Al = PHASE1 ? g_x_lo : g_h_lo;
    const __nv_bfloat16* Bh = PHASE1 ? g_w1_hi : g_w2_hi;
    const __nv_bfloat16* Bl = PHASE1 ? g_w1_lo : g_w2_lo;

    const int e   = blockIdx.z;
    const int cnt = g_cnt[e];
    const int m0  = blockIdx.y * 128;
    if (m0 >= cnt) return;
    const int n0  = blockIdx.x * 128;
    const int tid = threadIdx.x;

    extern __shared__ char smraw[];
    char* tilep = (char*)(((uintptr_t)smraw + 1023) & ~(uintptr_t)1023);
    const uint32_t sbase = smem_u32(tilep);
    __shared__ float s_bias[128];
    if (tid < 128) s_bias[tid] = bias[(size_t)e * ND + n0 + tid];

    // ---- load mapping: thread covers 16B seg (t&7) of rows (t>>3)+32p ----
    const int seg = tid & 7;
    const int rg  = tid >> 3;
    size_t   aoff[4], boff[4];
    uint32_t avalid[4], swzo[4];
#pragma unroll
    for (int p = 0; p < 4; p++) {
        int r   = rg + 32 * p;
        int idx = m0 + r;
        int a   = (idx < cnt) ? g_list[e][idx] : 0;
        int ra  = PHASE1 ? (a >> 1) : a;
        avalid[p] = (idx < cnt) ? 16u : 0u;
        aoff[p]   = (size_t)ra * KD + seg * 8;
        boff[p]   = ((size_t)e * ND + n0 + r) * KD + seg * 8;
        int o     = r * 128 + seg * 16;
        swzo[p]   = SWZ(o);
    }

    // ---- fragment addressing ----
    const int lane = tid & 31;
    const int wid  = tid >> 5;
    const int wm   = wid >> 1;       // 0..3  (m offset wm*32)
    const int wn   = wid & 1;        // 0..1  (n offset wn*64)
    uint32_t abase[2], axor[2], bbase[4], bxor[4];
#pragma unroll
    for (int mf = 0; mf < 2; mf++) {
        int row   = wm * 32 + mf * 16 + (lane & 15);
        abase[mf] = row * 128 + (lane >> 4) * 16;
        axor[mf]  = (row & 7) << 4;
    }
#pragma unroll
    for (int p = 0; p < 4; p++) {
        int row  = wn * 64 + p * 16 + (lane & 15);
        bbase[p] = row * 128 + (lane >> 4) * 16;
        bxor[p]  = (row & 7) << 4;
    }

    float acc[2][8][4];
#pragma unroll
    for (int i = 0; i < 2; i++)
#pragma unroll
        for (int j = 0; j < 8; j++)
#pragma unroll
            for (int q = 0; q < 4; q++) acc[i][j][q] = 0.f;

    // ---- prologue: load chunk 0 ----
    {
        uint32_t sb = sbase;
#pragma unroll
        for (int p = 0; p < 4; p++) {
            cp16(sb + swzo[p],          Ah + aoff[p], avalid[p]);
            cp16(sb + 16384 + swzo[p],  Al + aoff[p], avalid[p]);
            cp16(sb + 32768 + swzo[p],  Bh + boff[p], 16u);
            cp16(sb + 49152 + swzo[p],  Bl + boff[p], 16u);
        }
        CP_COMMIT();
    }

    for (int c = 0; c < NCH; ++c) {
        if (c + 1 < NCH) {
            const size_t koff = (size_t)(c + 1) * 64;
            uint32_t sb = sbase + ((c + 1) & 1) * STG;
#pragma unroll
            for (int p = 0; p < 4; p++) {
                cp16(sb + swzo[p],          Ah + aoff[p] + koff, avalid[p]);
                cp16(sb + 16384 + swzo[p],  Al + aoff[p] + koff, avalid[p]);
                cp16(sb + 32768 + swzo[p],  Bh + boff[p] + koff, 16u);
                cp16(sb + 49152 + swzo[p],  Bl + boff[p] + koff, 16u);
            }
            CP_COMMIT();
            CP_WAIT(1);
        } else {
            CP_WAIT(0);
        }
        __syncthreads();

        const uint32_t sb = sbase + (c & 1) * STG;
#pragma unroll
        for (int kk = 0; kk < 4; kk++) {
            uint32_t ah[2][4], al[2][4], bh[4][4], bl[4][4];
#pragma unroll
            for (int mf = 0; mf < 2; mf++) {
                uint32_t o = (abase[mf] + kk * 32) ^ axor[mf];
                ldsm4(ah[mf], sb + o);
                ldsm4(al[mf], sb + 16384 + o);
            }
#pragma unroll
            for (int p = 0; p < 4; p++) {
                uint32_t o = (bbase[p] + kk * 32) ^ bxor[p];
                ldsm4(bh[p], sb + 32768 + o);
                ldsm4(bl[p], sb + 49152 + o);
            }
            // term 1: Ah * Bh  (each acc touched once per term -> reuse dist 16)
#pragma unroll
            for (int mf = 0; mf < 2; mf++)
#pragma unroll
                for (int p = 0; p < 4; p++) {
                    mma16816(acc[mf][2 * p],     ah[mf], bh[p][0], bh[p][2]);
                    mma16816(acc[mf][2 * p + 1], ah[mf], bh[p][1], bh[p][3]);
                }
            // term 2: Ah * Bl
#pragma unroll
            for (int mf = 0; mf < 2; mf++)
#pragma unroll
                for (int p = 0; p < 4; p++) {
                    mma16816(acc[mf][2 * p],     ah[mf], bl[p][0], bl[p][2]);
                    mma16816(acc[mf][2 * p + 1], ah[mf], bl[p][1], bl[p][3]);
                }
            // term 3: Al * Bh
#pragma unroll
            for (int mf = 0; mf < 2; mf++)
#pragma unroll
                for (int p = 0; p < 4; p++) {
                    mma16816(acc[mf][2 * p],     al[mf], bh[p][0], bh[p][2]);
                    mma16816(acc[mf][2 * p + 1], al[mf], bh[p][1], bh[p][3]);
                }
        }
        __syncthreads();
    }

    // ---- epilogue ----
    const int quad = lane >> 2;
    const int qid  = lane & 3;
    const int ncol0 = wn * 64;     // CTA-local n base for this warp

#pragma unroll
    for (int mf = 0; mf < 2; mf++) {
#pragma unroll
        for (int rv = 0; rv < 2; rv++) {           // +0 / +8 rows
            int midx = m0 + wm * 32 + mf * 16 + rv * 8 + quad;
            if (midx >= cnt) continue;
            int a = g_list[e][midx];
            if (PHASE1) {
                __nv_bfloat16* dh = g_h_hi + (size_t)a * HID + n0;
                __nv_bfloat16* dl = g_h_lo + (size_t)a * HID + n0;
#pragma unroll
                for (int nf = 0; nf < 8; nf++) {
                    int nloc = ncol0 + nf * 8 + 2 * qid;
                    float v0 = fmaxf(acc[mf][nf][2 * rv]     + s_bias[nloc],     0.f);
                    float v1 = fmaxf(acc[mf][nf][2 * rv + 1] + s_bias[nloc + 1], 0.f);
                    __nv_bfloat16 h0 = __float2bfloat16(v0), h1 = __float2bfloat16(v1);
                    *reinterpret_cast<uint32_t*>(dh + nloc) = pack_bf2(v0, v1);
                    *reinterpret_cast<uint32_t*>(dl + nloc) =
                        pack_bf2(v0 - __bfloat162float(h0), v1 - __bfloat162float(h1));
                }
            } else {
                float w = g_wgt[a];
                float* op = out + (size_t)(a >> 1) * DIM + n0;
#pragma unroll
                for (int nf = 0; nf < 8; nf++) {
                    int nloc = ncol0 + nf * 8 + 2 * qid;
                    atomicAdd(op + nloc,     (acc[mf][nf][2 * rv]     + s_bias[nloc])     * w);
                    atomicAdd(op + nloc + 1, (acc[mf][nf][2 * rv + 1] + s_bias[nloc + 1]) * w);
                }
            }
        }
    }
}

// ---------------- launch ----------------
extern "C" void kernel_launch(void* const* d_in, const int* in_sizes, int n_in,
                              void* d_out, int out_size) {
    const float* x  = (const float*)d_in[0];
    const float* Wg = (const float*)d_in[1];
    const float* bg = (const float*)d_in[2];
    const float* W1 = (const float*)d_in[3];
    const float* b1 = (const float*)d_in[4];
    const float* W2 = (const float*)d_in[5];
    const float* b2 = (const float*)d_in[6];
    float* out = (float*)d_out;

    const int SMEM_BYTES = 2 * 64 * 1024 + 1024;
    cudaFuncSetAttribute((const void*)moe_gemm<true>,
                         cudaFuncAttributeMaxDynamicSharedMemorySize, SMEM_BYTES);
    cudaFuncSetAttribute((const void*)moe_gemm<false>,
                         cudaFuncAttributeMaxDynamicSharedMemorySize, SMEM_BYTES);

    __nv_bfloat16 *w1h, *w1l, *w2h, *w2l;
    cudaGetSymbolAddress((void**)&w1h, g_w1_hi);
    cudaGetSymbolAddress((void**)&w1l, g_w1_lo);
    cudaGetSymbolAddress((void**)&w2h, g_w2_hi);
    cudaGetSymbolAddress((void**)&w2l, g_w2_lo);

    zero_kernel<<<(NTOK * DIM) / (256 * 4), 256>>>(out);
    conv_x<<<(NTOK * DIM) / (256 * 8), 256>>>(x);
    // W1 [e][D][H] -> [e][H][D];  W2 [e][H][D] -> [e][D][H]
    conv_w<<<dim3(HID / 32, DIM / 32, NEXP), dim3(16, 16)>>>(W1, w1h, w1l, DIM, HID);
    conv_w<<<dim3(DIM / 32, HID / 32, NEXP), dim3(16, 16)>>>(W2, w2h, w2l, HID, DIM);
    gating_kernel<<<(NTOK * 32) / 256, 256>>>(x, Wg, bg);

    moe_gemm<true><<<dim3(HID / 128, MAXA / 128, NEXP), 256, SMEM_BYTES>>>(b1, nullptr);
    moe_gemm<false><<<dim3(DIM / 128, MAXA / 128, NEXP), 256, SMEM_BYTES>>>(b2, out);
}